// round 14
// baseline (speedup 1.0000x reference)
#include <cuda_runtime.h>
#include <math.h>

#define N_TOK 4096
#define D_DIM 2048
#define N_EXP 8
#define TOPK  2
#define CAP   512
#define PITCH 2052                 // padded W smem row (floats)
#define BLK1  768                  // 24 warps: 16 GEMM + 8 fill
#define GRID1 128                  // 1 block/SM, single balanced wave

__device__ int g_choice[N_TOK * TOPK];
__device__ unsigned int g_done;    // epoch counter (never reset; replay-safe)

__device__ __forceinline__ unsigned long long fma2(
        unsigned long long a, unsigned long long b, unsigned long long c) {
    unsigned long long d;
    asm("fma.rn.f32x2 %0, %1, %2, %3;" : "=l"(d) : "l"(a), "l"(b), "l"(c));
    return d;
}

// ---------------------------------------------------------------------------
// Single fused kernel:
//   warps 0-15 : logits GEMM (2 tok/warp, f32x2 FMA vs smem-transposed W),
//                top-2 + softmax, writes gates/indices/g_choice.
//   warps 16-23: zero this block's 512 KB dispatcher slice concurrently.
//   epoch barrier; then blocks 0-15 run the per-(k,e) capacity scan and
//   scatter the 1.0f entries. (R13 k_fused + R5 barrier/scan, both proven.)
// ---------------------------------------------------------------------------
__global__ __launch_bounds__(BLK1) void k_fused(
        const float* __restrict__ x,
        const float* __restrict__ W,
        float* __restrict__ out) {
    __shared__ float wt[N_EXP * PITCH];   // 65.7 KB
    __shared__ int warp_sums[16];

    int tid  = threadIdx.x;
    int lane = tid & 31;
    int wrp  = tid >> 5;
    int bid  = blockIdx.x;

    // stage ALL of W transposed: wt[e][d]  (all 24 warps help)
    for (int idx = tid; idx < D_DIM * N_EXP; idx += BLK1) {
        int d = idx >> 3;
        int e = idx & 7;
        wt[e * PITCH + d] = W[idx];
    }
    __syncthreads();

    if (wrp >= 16) {
        // ---------------- fill warps: zero 64 KB each ----------------
        int f = wrp - 16;
        float4* z4 = reinterpret_cast<float4*>(out);
        size_t base = (size_t)bid * 32768 + f * 4096 + lane;   // f4 units
        const float4 zero = make_float4(0.f, 0.f, 0.f, 0.f);
        #pragma unroll 8
        for (int i = 0; i < 128; i++)
            z4[base + i * 32] = zero;
    } else {
        // ---------------- GEMM warps: 2 tokens each ----------------
        int t0 = (bid * 16 + wrp) * 2;
        const ulonglong2* xr0 = reinterpret_cast<const ulonglong2*>(x) + (size_t)t0 * (D_DIM / 4);
        const ulonglong2* xr1 = xr0 + (D_DIM / 4);

        unsigned long long acc0[N_EXP] = {};
        unsigned long long acc1[N_EXP] = {};

        // double-buffered 2-j prefetch: 4 LDG.128 in flight per warp
        ulonglong2 xa[2][2], xb[2][2];
        xa[0][0] = xr0[lane];      xb[0][0] = xr1[lane];
        xa[0][1] = xr0[32 + lane]; xb[0][1] = xr1[32 + lane];

        #pragma unroll
        for (int jj = 0; jj < 8; jj++) {
            int cur = jj & 1, nxt = cur ^ 1;
            if (jj < 7) {
                int j2 = (jj + 1) * 2;
                xa[nxt][0] = xr0[(j2    ) * 32 + lane];
                xb[nxt][0] = xr1[(j2    ) * 32 + lane];
                xa[nxt][1] = xr0[(j2 + 1) * 32 + lane];
                xb[nxt][1] = xr1[(j2 + 1) * 32 + lane];
            }
            #pragma unroll
            for (int u = 0; u < 2; u++) {
                int dbase = ((jj * 2 + u) * 32 + lane) * 4;
                #pragma unroll
                for (int e = 0; e < N_EXP; e++) {
                    ulonglong2 w = *reinterpret_cast<const ulonglong2*>(&wt[e * PITCH + dbase]);
                    acc0[e] = fma2(xa[cur][u].x, w.x, acc0[e]);
                    acc0[e] = fma2(xa[cur][u].y, w.y, acc0[e]);
                    acc1[e] = fma2(xb[cur][u].x, w.x, acc1[e]);
                    acc1[e] = fma2(xb[cur][u].y, w.y, acc1[e]);
                }
            }
        }

        // horizontal add + butterfly reduce
        float logit[2][N_EXP];
        #pragma unroll
        for (int e = 0; e < N_EXP; e++) {
            float s0 = __uint_as_float((unsigned int)(acc0[e] & 0xffffffffull)) +
                       __uint_as_float((unsigned int)(acc0[e] >> 32));
            float s1 = __uint_as_float((unsigned int)(acc1[e] & 0xffffffffull)) +
                       __uint_as_float((unsigned int)(acc1[e] >> 32));
            #pragma unroll
            for (int off = 16; off > 0; off >>= 1) {
                s0 += __shfl_xor_sync(0xffffffffu, s0, off);
                s1 += __shfl_xor_sync(0xffffffffu, s1, off);
            }
            logit[0][e] = s0;
            logit[1][e] = s1;
        }

        if (lane == 0) {
            float* gate = out + (size_t)N_TOK * N_EXP * CAP;
            float* idxf = gate + N_TOK * TOPK;
            #pragma unroll
            for (int t = 0; t < 2; t++) {
                int tok = t0 + t;
                float best = -INFINITY, sec = -INFINITY;
                int bi = 0, si = 0;
                #pragma unroll
                for (int e = 0; e < N_EXP; e++) {
                    float v = logit[t][e];
                    if (v > best)     { sec = best; si = bi; best = v; bi = e; }
                    else if (v > sec) { sec = v;    si = e; }
                }
                float g0 = 1.0f / (1.0f + expf(sec - best));
                gate[tok * 2 + 0] = g0;
                gate[tok * 2 + 1] = 1.0f - g0;
                idxf[tok * 2 + 0] = (float)bi;
                idxf[tok * 2 + 1] = (float)si;
                g_choice[tok * 2 + 0] = bi;
                g_choice[tok * 2 + 1] = si;
            }
        }
    }

    // ---------------- epoch barrier (R5-proven, replay-safe) ----------------
    __threadfence();          // all zero-stores + g_choice writes visible
    __syncthreads();
    if (bid >= 16) {
        if (tid == 0) atomicAdd(&g_done, 1u);
        return;
    }
    if (tid == 0) {
        unsigned int old = atomicAdd(&g_done, 1u);
        unsigned int target = (old / GRID1) * GRID1 + GRID1;
        while (atomicAdd(&g_done, 0u) < target) { }
    }
    __syncthreads();
    __threadfence();

    // ---------------- scan + scatter: block = (k,e) pair (R5-proven) --------
    int k = bid >> 3;
    int e = bid & 7;

    if (tid < 512) {
        int n0 = tid * 8;                 // 512 threads * 8 tokens = 4096
        int flags[8];
        int localex[8];
        int s = 0;
        #pragma unroll
        for (int j = 0; j < 8; j++) {
            flags[j]   = (g_choice[(n0 + j) * 2 + k] == e) ? 1 : 0;
            localex[j] = s;
            s += flags[j];
        }

        int inc = s;
        #pragma unroll
        for (int off = 1; off < 32; off <<= 1) {
            int v = __shfl_up_sync(0xffffffffu, inc, off);
            if (lane >= off) inc += v;
        }
        if (lane == 31) warp_sums[wrp] = inc;
        __syncthreads();

        if (wrp == 0 && lane < 16) {
            int v = warp_sums[lane];
            int winc = v;
            #pragma unroll
            for (int off = 1; off < 16; off <<= 1) {
                int u = __shfl_up_sync(0x0000ffffu, winc, off);
                if (lane >= off) winc += u;
            }
            warp_sums[lane] = winc - v;   // exclusive warp offsets
        }
        __syncthreads();

        int thread_prefix = warp_sums[wrp] + (inc - s);

        #pragma unroll
        for (int j = 0; j < 8; j++) {
            if (flags[j]) {
                int pri = thread_prefix + localex[j] + 1;   // 1-based priority
                if (pri <= CAP)
                    out[(size_t)(n0 + j) * (N_EXP * CAP) + e * CAP + (pri - 1)] = 1.0f;
            }
        }
    }
}

// ---------------------------------------------------------------------------
extern "C" void kernel_launch(void* const* d_in, const int* in_sizes, int n_in,
                              void* d_out, int out_size) {
    const float* x = (const float*)d_in[0];   // [4096, 2048]
    const float* W = (const float*)d_in[1];   // [2048, 8]
    float* out = (float*)d_out;

    k_fused<<<GRID1, BLK1>>>(x, W, out);
}